// round 10
// baseline (speedup 1.0000x reference)
#include <cuda_runtime.h>
#include <cuda_bf16.h>
#include <mma.h>
#include <float.h>
#include <stdint.h>

using namespace nvcuda;

#define N_NODES 50000
#define N_PAD   50048          // 391 * 128: GEMM tiles store full tiles into g_h
#define N_EDGES 640000
#define D       128
#define OUTF    128
#define K2      256
#define TM      128
#define LDS_K   48             // bf16 row stride (48 elems = 96B, mult of 16B)

// ---------------- device scratch ----------------
__device__ __align__(16) float g_h[N_PAD * D];         // fc_pool output (padded)
__device__ __align__(16) float g_neigh[N_NODES * D];   // max-pooled messages
__device__ int   g_deg[N_NODES];
__device__ int   g_start[N_NODES + 1];
__device__ int   g_cursor[N_NODES];
__device__ __align__(16) int   g_ssrc[N_EDGES];
__device__ __align__(16) float g_sw[N_EDGES];

__device__ __forceinline__ int clampN(int v) { return min(max(v, 0), N_NODES - 1); }

// ---------------- CSR build ----------------
__global__ void zero_deg_kernel() {
    int i = blockIdx.x * blockDim.x + threadIdx.x;
    if (i < N_NODES) g_deg[i] = 0;
}

__global__ void hist_kernel(const int* __restrict__ dst) {
    int e = blockIdx.x * blockDim.x + threadIdx.x;
    if (e < N_EDGES) atomicAdd(&g_deg[clampN(dst[e])], 1);
}

// single block: thread-serial chunks + one 1024-wide block scan (~20 syncs)
__global__ __launch_bounds__(1024) void scan_kernel() {
    __shared__ int ssum[1024];
    const int tid = threadIdx.x;
    const int CH = (N_NODES + 1023) / 1024;  // 49
    int base = tid * CH;
    int s = 0;
    for (int i = 0; i < CH; i++) {
        int idx = base + i;
        if (idx < N_NODES) s += g_deg[idx];
    }
    ssum[tid] = s;
    __syncthreads();
    #pragma unroll
    for (int off = 1; off < 1024; off <<= 1) {
        int v = (tid >= off) ? ssum[tid - off] : 0;
        __syncthreads();
        ssum[tid] += v;
        __syncthreads();
    }
    int run = ssum[tid] - s;   // exclusive prefix of this chunk
    for (int i = 0; i < CH; i++) {
        int idx = base + i;
        if (idx < N_NODES) {
            g_start[idx] = run; g_cursor[idx] = run;
            run += g_deg[idx];
        }
    }
    if (tid == 1023) g_start[N_NODES] = run;
}

__global__ void scatter_kernel(const int* __restrict__ src, const int* __restrict__ dst,
                               const float* __restrict__ weight) {
    int e = blockIdx.x * blockDim.x + threadIdx.x;
    if (e >= N_EDGES) return;
    int d = clampN(dst[e]);
    int pos = atomicAdd(&g_cursor[d], 1);
    g_ssrc[pos] = clampN(src[e]);
    g_sw[pos]   = weight[e];
}

// ---------------- per-node max reduce: 2 nodes/block, MLP=8 ----------------
__global__ __launch_bounds__(256) void reduce_kernel() {
    int node = blockIdx.x * 2 + (threadIdx.x >> 7);
    int tid  = threadIdx.x & 127;
    if (node >= N_NODES) return;
    int beg = g_start[node], end = g_start[node + 1];
    float acc = -FLT_MAX;
    int i = beg;
    for (; i + 8 <= end; i += 8) {
        int   s0 = g_ssrc[i],   s1 = g_ssrc[i+1], s2 = g_ssrc[i+2], s3 = g_ssrc[i+3];
        int   s4 = g_ssrc[i+4], s5 = g_ssrc[i+5], s6 = g_ssrc[i+6], s7 = g_ssrc[i+7];
        float w0 = g_sw[i],   w1 = g_sw[i+1], w2 = g_sw[i+2], w3 = g_sw[i+3];
        float w4 = g_sw[i+4], w5 = g_sw[i+5], w6 = g_sw[i+6], w7 = g_sw[i+7];
        float v0 = g_h[s0*D + tid], v1 = g_h[s1*D + tid], v2 = g_h[s2*D + tid], v3 = g_h[s3*D + tid];
        float v4 = g_h[s4*D + tid], v5 = g_h[s5*D + tid], v6 = g_h[s6*D + tid], v7 = g_h[s7*D + tid];
        acc = fmaxf(acc, v0 * w0); acc = fmaxf(acc, v1 * w1);
        acc = fmaxf(acc, v2 * w2); acc = fmaxf(acc, v3 * w3);
        acc = fmaxf(acc, v4 * w4); acc = fmaxf(acc, v5 * w5);
        acc = fmaxf(acc, v6 * w6); acc = fmaxf(acc, v7 * w7);
    }
    if (i + 4 <= end) {
        int   s0 = g_ssrc[i],   s1 = g_ssrc[i+1], s2 = g_ssrc[i+2], s3 = g_ssrc[i+3];
        float w0 = g_sw[i],     w1 = g_sw[i+1],   w2 = g_sw[i+2],   w3 = g_sw[i+3];
        float v0 = g_h[s0*D + tid], v1 = g_h[s1*D + tid];
        float v2 = g_h[s2*D + tid], v3 = g_h[s3*D + tid];
        acc = fmaxf(acc, v0 * w0); acc = fmaxf(acc, v1 * w1);
        acc = fmaxf(acc, v2 * w2); acc = fmaxf(acc, v3 * w3);
        i += 4;
    }
    for (; i < end; i++)
        acc = fmaxf(acc, g_h[g_ssrc[i]*D + tid] * g_sw[i]);
    g_neigh[node*D + tid] = (beg == end) ? 0.f : acc;
}

// ---------------- wmma bf16 3-pass GEMM: out = A @ W^T + bias ----------------
// CTA: 128x128, 256 threads = 8 warps (4m x 2n), warp tile 32x64, K chunks of 32.
// D = AhiBhi + AloBhi + AhiBlo  (missing AloBlo ~ 2^-18 rel).
// TO_GH writes via device-symbol reference (host-arg shadow-pointer trap!).
static constexpr int SM_REG   = 128 * LDS_K;             // elems per bf16 region
static constexpr int SM_F_OFF = 4 * SM_REG * 2;          // 49152 bytes
static constexpr int SMEM_SZ  = SM_F_OFF + 16 * 128 * 4; // 57344 bytes

template<int KTOT, bool CONCAT, bool TO_GH>
__global__ __launch_bounds__(256) void gemm_wmma_kernel(const float* __restrict__ A0,
                                                        const float* __restrict__ W,
                                                        const float* __restrict__ bias,
                                                        float* __restrict__ outp) {
    extern __shared__ char smem[];
    __nv_bfloat16* sAhi = (__nv_bfloat16*)smem;
    __nv_bfloat16* sAlo = sAhi + SM_REG;
    __nv_bfloat16* sBhi = sAlo + SM_REG;
    __nv_bfloat16* sBlo = sBhi + SM_REG;
    float*         sF   = (float*)(smem + SM_F_OFF);     // bias tile / store staging

    const int tid  = threadIdx.x;
    const int lane = tid & 31;
    const int wid  = tid >> 5;
    const int wm   = wid >> 1;          // 0..3 -> rows wm*32
    const int wn   = wid & 1;           // 0..1 -> cols wn*64
    const int row0 = blockIdx.x * TM;

    float* dstp = TO_GH ? g_h : outp;   // device-side symbol reference

    for (int i = tid; i < 16 * 128; i += 256) sF[i] = bias[i & 127];
    __syncthreads();

    wmma::fragment<wmma::accumulator, 16, 16, 16, float> acc[2][4];
    #pragma unroll
    for (int mt = 0; mt < 2; mt++)
        #pragma unroll
        for (int nt = 0; nt < 4; nt++)
            wmma::load_matrix_sync(acc[mt][nt], sF + wn * 64 + nt * 16, 128, wmma::mem_row_major);

    constexpr int NCHUNK = KTOT / 32;
    for (int c = 0; c < NCHUNK; c++) {
        const int k0 = c * 32;
        const float* Asrc = (!CONCAT || k0 < D) ? A0 : g_neigh;
        const int    koff = (!CONCAT || k0 < D) ? k0 : (k0 - D);
        __syncthreads();                 // prev chunk fully consumed

        #pragma unroll
        for (int t = 0; t < 4; t++) {    // A: 1024 granules of 4 floats
            int g = tid + t * 256;
            int row = g >> 3, kc = (g & 7) * 4;
            int grow = row0 + row;
            float4 v = (grow < N_NODES) ? *(const float4*)&Asrc[grow * D + koff + kc]
                                        : make_float4(0.f, 0.f, 0.f, 0.f);
            __nv_bfloat16 h0 = __float2bfloat16_rn(v.x), h1 = __float2bfloat16_rn(v.y);
            __nv_bfloat16 h2 = __float2bfloat16_rn(v.z), h3 = __float2bfloat16_rn(v.w);
            __nv_bfloat16 l0 = __float2bfloat16_rn(v.x - __bfloat162float(h0));
            __nv_bfloat16 l1 = __float2bfloat16_rn(v.y - __bfloat162float(h1));
            __nv_bfloat16 l2 = __float2bfloat16_rn(v.z - __bfloat162float(h2));
            __nv_bfloat16 l3 = __float2bfloat16_rn(v.w - __bfloat162float(h3));
            int o = row * LDS_K + kc;
            *(__nv_bfloat162*)&sAhi[o]     = __nv_bfloat162(h0, h1);
            *(__nv_bfloat162*)&sAhi[o + 2] = __nv_bfloat162(h2, h3);
            *(__nv_bfloat162*)&sAlo[o]     = __nv_bfloat162(l0, l1);
            *(__nv_bfloat162*)&sAlo[o + 2] = __nv_bfloat162(l2, l3);
        }
        #pragma unroll
        for (int t = 0; t < 4; t++) {    // B: W[n][k]
            int g = tid + t * 256;
            int row = g >> 3, kc = (g & 7) * 4;
            float4 v = *(const float4*)&W[row * KTOT + k0 + kc];
            __nv_bfloat16 h0 = __float2bfloat16_rn(v.x), h1 = __float2bfloat16_rn(v.y);
            __nv_bfloat16 h2 = __float2bfloat16_rn(v.z), h3 = __float2bfloat16_rn(v.w);
            __nv_bfloat16 l0 = __float2bfloat16_rn(v.x - __bfloat162float(h0));
            __nv_bfloat16 l1 = __float2bfloat16_rn(v.y - __bfloat162float(h1));
            __nv_bfloat16 l2 = __float2bfloat16_rn(v.z - __bfloat162float(h2));
            __nv_bfloat16 l3 = __float2bfloat16_rn(v.w - __bfloat162float(h3));
            int o = row * LDS_K + kc;
            *(__nv_bfloat162*)&sBhi[o]     = __nv_bfloat162(h0, h1);
            *(__nv_bfloat162*)&sBhi[o + 2] = __nv_bfloat162(h2, h3);
            *(__nv_bfloat162*)&sBlo[o]     = __nv_bfloat162(l0, l1);
            *(__nv_bfloat162*)&sBlo[o + 2] = __nv_bfloat162(l2, l3);
        }
        __syncthreads();

        #pragma unroll
        for (int ks = 0; ks < 2; ks++) {
            const int k16 = ks * 16;
            wmma::fragment<wmma::matrix_a, 16, 16, 16, __nv_bfloat16, wmma::row_major> ahi[2], alo[2];
            #pragma unroll
            for (int mt = 0; mt < 2; mt++) {
                int r = wm * 32 + mt * 16;
                wmma::load_matrix_sync(ahi[mt], &sAhi[r * LDS_K + k16], LDS_K);
                wmma::load_matrix_sync(alo[mt], &sAlo[r * LDS_K + k16], LDS_K);
            }
            #pragma unroll
            for (int nt = 0; nt < 4; nt++) {
                int n = wn * 64 + nt * 16;
                wmma::fragment<wmma::matrix_b, 16, 16, 16, __nv_bfloat16, wmma::col_major> bhi, blo;
                wmma::load_matrix_sync(bhi, &sBhi[n * LDS_K + k16], LDS_K);
                wmma::load_matrix_sync(blo, &sBlo[n * LDS_K + k16], LDS_K);
                #pragma unroll
                for (int mt = 0; mt < 2; mt++) {
                    wmma::mma_sync(acc[mt][nt], ahi[mt], bhi, acc[mt][nt]);
                    wmma::mma_sync(acc[mt][nt], alo[mt], bhi, acc[mt][nt]);
                    wmma::mma_sync(acc[mt][nt], ahi[mt], blo, acc[mt][nt]);
                }
            }
        }
    }

    // epilogue
    __syncthreads();                     // bias tile no longer needed -> staging reuse
    #pragma unroll
    for (int mt = 0; mt < 2; mt++) {
        int r0 = row0 + wm * 32 + mt * 16;
        #pragma unroll
        for (int nt = 0; nt < 4; nt++) {
            int c0 = wn * 64 + nt * 16;
            if (TO_GH || r0 + 16 <= N_NODES) {
                wmma::store_matrix_sync(&dstp[r0 * OUTF + c0], acc[mt][nt], OUTF, wmma::mem_row_major);
            } else {
                float* st = sF + wid * 256;     // private 16x16 staging per warp
                wmma::store_matrix_sync(st, acc[mt][nt], 16, wmma::mem_row_major);
                __syncwarp();
                for (int i = lane; i < 256; i += 32) {
                    int rr = r0 + (i >> 4);
                    if (rr < N_NODES) dstp[rr * OUTF + c0 + (i & 15)] = st[i];
                }
                __syncwarp();
            }
        }
    }
}

// ---------------- launch ----------------
extern "C" void kernel_launch(void* const* d_in, const int* in_sizes, int n_in,
                              void* d_out, int out_size) {
    const float* feat    = (const float*)d_in[0];
    const float* weight  = (const float*)d_in[1];
    const int*   src     = (const int*)d_in[2];
    const int*   dst     = (const int*)d_in[3];
    const float* W_pool  = (const float*)d_in[4];
    const float* b_pool  = (const float*)d_in[5];
    const float* W_neigh = (const float*)d_in[6];
    const float* b_neigh = (const float*)d_in[7];
    float*       out     = (float*)d_out;

    cudaFuncSetAttribute(gemm_wmma_kernel<D,  false, true>,
                         cudaFuncAttributeMaxDynamicSharedMemorySize, SMEM_SZ);
    cudaFuncSetAttribute(gemm_wmma_kernel<K2, true,  false>,
                         cudaFuncAttributeMaxDynamicSharedMemorySize, SMEM_SZ);

    const int GEMM_GRID = (N_NODES + TM - 1) / TM;   // 391

    zero_deg_kernel<<<(N_NODES + 255) / 256, 256>>>();
    hist_kernel<<<(N_EDGES + 255) / 256, 256>>>(dst);
    scan_kernel<<<1, 1024>>>();
    scatter_kernel<<<(N_EDGES + 255) / 256, 256>>>(src, dst, weight);

    gemm_wmma_kernel<D, false, true><<<GEMM_GRID, 256, SMEM_SZ>>>(feat, W_pool, b_pool, nullptr);

    reduce_kernel<<<(N_NODES + 1) / 2, 256>>>();

    gemm_wmma_kernel<K2, true, false><<<GEMM_GRID, 256, SMEM_SZ>>>(feat, W_neigh, b_neigh, out);
}

// round 11
// speedup vs baseline: 1.2242x; 1.2242x over previous
#include <cuda_runtime.h>
#include <cuda_bf16.h>
#include <mma.h>
#include <float.h>
#include <stdint.h>

using namespace nvcuda;

#define N_NODES 50000
#define N_PAD   50048          // 391 * 128: GEMM tiles store full tiles into g_h
#define N_EDGES 640000
#define D       128
#define OUTF    128
#define K2      256
#define TM      128
#define LDS_K   48             // bf16 row stride (48 elems = 96B, mult of 16B)

// ---------------- device scratch ----------------
__device__ __align__(16) float g_h[N_PAD * D];         // fc_pool output (padded)
__device__ __align__(16) float g_neigh[N_NODES * D];   // max-pooled messages
__device__ int   g_deg[N_NODES];
__device__ int   g_start[N_NODES + 1];
__device__ int   g_cursor[N_NODES];
__device__ __align__(16) int   g_ssrc[N_EDGES];
__device__ __align__(16) float g_sw[N_EDGES];

__device__ __forceinline__ int clampN(int v) { return min(max(v, 0), N_NODES - 1); }

// ---------------- CSR build (R4-verbatim) ----------------
__global__ void zero_deg_kernel() {
    int i = blockIdx.x * blockDim.x + threadIdx.x;
    if (i < N_NODES) g_deg[i] = 0;
}

__global__ void hist_kernel(const int* __restrict__ dst) {
    int e = blockIdx.x * blockDim.x + threadIdx.x;
    if (e < N_EDGES) atomicAdd(&g_deg[clampN(dst[e])], 1);
}

// R4-verbatim single-block scan (known-good, coalesced)
__global__ void scan_kernel() {
    __shared__ int sh[1024];
    __shared__ int s_carry;
    int tid = threadIdx.x;
    if (tid == 0) s_carry = 0;
    __syncthreads();
    for (int base = 0; base < N_NODES; base += 1024) {
        int idx = base + tid;
        int v = (idx < N_NODES) ? g_deg[idx] : 0;
        sh[tid] = v;
        __syncthreads();
        #pragma unroll
        for (int off = 1; off < 1024; off <<= 1) {
            int t = (tid >= off) ? sh[tid - off] : 0;
            __syncthreads();
            sh[tid] += t;
            __syncthreads();
        }
        int excl = sh[tid] - v;
        int c = s_carry;
        if (idx < N_NODES) { g_start[idx] = c + excl; g_cursor[idx] = c + excl; }
        __syncthreads();
        if (tid == 1023) s_carry = c + sh[1023];
        __syncthreads();
    }
    if (tid == 0) g_start[N_NODES] = s_carry;
}

__global__ void scatter_kernel(const int* __restrict__ src, const int* __restrict__ dst,
                               const float* __restrict__ weight) {
    int e = blockIdx.x * blockDim.x + threadIdx.x;
    if (e >= N_EDGES) return;
    int d = clampN(dst[e]);
    int pos = atomicAdd(&g_cursor[d], 1);
    g_ssrc[pos] = clampN(src[e]);
    g_sw[pos]   = weight[e];
}

// ---------------- warp-per-node max reduce, float4 gather ----------------
// lane l owns cols [4l, 4l+4): one LDG.128 per edge per warp (vs 4 LDG.32 waves before)
__global__ __launch_bounds__(256) void reduce_kernel() {
    const int node = (blockIdx.x << 3) + (threadIdx.x >> 5);
    const int lane = threadIdx.x & 31;
    if (node >= N_NODES) return;
    const int beg = g_start[node], end = g_start[node + 1];
    const int col = lane * 4;
    float4 acc = make_float4(-FLT_MAX, -FLT_MAX, -FLT_MAX, -FLT_MAX);
    int i = beg;
    for (; i + 4 <= end; i += 4) {                       // MLP = 4 x LDG.128
        int   s0 = g_ssrc[i],   s1 = g_ssrc[i+1], s2 = g_ssrc[i+2], s3 = g_ssrc[i+3];
        float w0 = g_sw[i],     w1 = g_sw[i+1],   w2 = g_sw[i+2],   w3 = g_sw[i+3];
        float4 v0 = *(const float4*)&g_h[s0*D + col];
        float4 v1 = *(const float4*)&g_h[s1*D + col];
        float4 v2 = *(const float4*)&g_h[s2*D + col];
        float4 v3 = *(const float4*)&g_h[s3*D + col];
        acc.x = fmaxf(acc.x, v0.x*w0); acc.y = fmaxf(acc.y, v0.y*w0);
        acc.z = fmaxf(acc.z, v0.z*w0); acc.w = fmaxf(acc.w, v0.w*w0);
        acc.x = fmaxf(acc.x, v1.x*w1); acc.y = fmaxf(acc.y, v1.y*w1);
        acc.z = fmaxf(acc.z, v1.z*w1); acc.w = fmaxf(acc.w, v1.w*w1);
        acc.x = fmaxf(acc.x, v2.x*w2); acc.y = fmaxf(acc.y, v2.y*w2);
        acc.z = fmaxf(acc.z, v2.z*w2); acc.w = fmaxf(acc.w, v2.w*w2);
        acc.x = fmaxf(acc.x, v3.x*w3); acc.y = fmaxf(acc.y, v3.y*w3);
        acc.z = fmaxf(acc.z, v3.z*w3); acc.w = fmaxf(acc.w, v3.w*w3);
    }
    for (; i < end; i++) {
        int s = g_ssrc[i];
        float w = g_sw[i];
        float4 v = *(const float4*)&g_h[s*D + col];
        acc.x = fmaxf(acc.x, v.x*w); acc.y = fmaxf(acc.y, v.y*w);
        acc.z = fmaxf(acc.z, v.z*w); acc.w = fmaxf(acc.w, v.w*w);
    }
    float4 outv = (beg == end) ? make_float4(0.f, 0.f, 0.f, 0.f) : acc;
    *(float4*)&g_neigh[node*D + col] = outv;
}

// ---------------- wmma bf16 3-pass GEMM (R9-verbatim) ----------------
static constexpr int SM_REG   = 128 * LDS_K;             // elems per bf16 region
static constexpr int SM_F_OFF = 4 * SM_REG * 2;          // 49152 bytes
static constexpr int SMEM_SZ  = SM_F_OFF + 16 * 128 * 4; // 57344 bytes

template<int KTOT, bool CONCAT, bool TO_GH>
__global__ __launch_bounds__(256) void gemm_wmma_kernel(const float* __restrict__ A0,
                                                        const float* __restrict__ W,
                                                        const float* __restrict__ bias,
                                                        float* __restrict__ outp) {
    extern __shared__ char smem[];
    __nv_bfloat16* sAhi = (__nv_bfloat16*)smem;
    __nv_bfloat16* sAlo = sAhi + SM_REG;
    __nv_bfloat16* sBhi = sAlo + SM_REG;
    __nv_bfloat16* sBlo = sBhi + SM_REG;
    float*         sF   = (float*)(smem + SM_F_OFF);     // bias tile / store staging

    const int tid  = threadIdx.x;
    const int lane = tid & 31;
    const int wid  = tid >> 5;
    const int wm   = wid >> 1;          // 0..3 -> rows wm*32
    const int wn   = wid & 1;           // 0..1 -> cols wn*64
    const int row0 = blockIdx.x * TM;

    float* dstp = TO_GH ? g_h : outp;   // device-side symbol reference (shadow-ptr trap!)

    for (int i = tid; i < 16 * 128; i += 256) sF[i] = bias[i & 127];
    __syncthreads();

    wmma::fragment<wmma::accumulator, 16, 16, 16, float> acc[2][4];
    #pragma unroll
    for (int mt = 0; mt < 2; mt++)
        #pragma unroll
        for (int nt = 0; nt < 4; nt++)
            wmma::load_matrix_sync(acc[mt][nt], sF + wn * 64 + nt * 16, 128, wmma::mem_row_major);

    constexpr int NCHUNK = KTOT / 32;
    for (int c = 0; c < NCHUNK; c++) {
        const int k0 = c * 32;
        const float* Asrc = (!CONCAT || k0 < D) ? A0 : g_neigh;
        const int    koff = (!CONCAT || k0 < D) ? k0 : (k0 - D);
        __syncthreads();                 // prev chunk fully consumed

        #pragma unroll
        for (int t = 0; t < 4; t++) {    // A: 1024 granules of 4 floats
            int g = tid + t * 256;
            int row = g >> 3, kc = (g & 7) * 4;
            int grow = row0 + row;
            float4 v = (grow < N_NODES) ? *(const float4*)&Asrc[grow * D + koff + kc]
                                        : make_float4(0.f, 0.f, 0.f, 0.f);
            __nv_bfloat16 h0 = __float2bfloat16_rn(v.x), h1 = __float2bfloat16_rn(v.y);
            __nv_bfloat16 h2 = __float2bfloat16_rn(v.z), h3 = __float2bfloat16_rn(v.w);
            __nv_bfloat16 l0 = __float2bfloat16_rn(v.x - __bfloat162float(h0));
            __nv_bfloat16 l1 = __float2bfloat16_rn(v.y - __bfloat162float(h1));
            __nv_bfloat16 l2 = __float2bfloat16_rn(v.z - __bfloat162float(h2));
            __nv_bfloat16 l3 = __float2bfloat16_rn(v.w - __bfloat162float(h3));
            int o = row * LDS_K + kc;
            *(__nv_bfloat162*)&sAhi[o]     = __nv_bfloat162(h0, h1);
            *(__nv_bfloat162*)&sAhi[o + 2] = __nv_bfloat162(h2, h3);
            *(__nv_bfloat162*)&sAlo[o]     = __nv_bfloat162(l0, l1);
            *(__nv_bfloat162*)&sAlo[o + 2] = __nv_bfloat162(l2, l3);
        }
        #pragma unroll
        for (int t = 0; t < 4; t++) {    // B: W[n][k]
            int g = tid + t * 256;
            int row = g >> 3, kc = (g & 7) * 4;
            float4 v = *(const float4*)&W[row * KTOT + k0 + kc];
            __nv_bfloat16 h0 = __float2bfloat16_rn(v.x), h1 = __float2bfloat16_rn(v.y);
            __nv_bfloat16 h2 = __float2bfloat16_rn(v.z), h3 = __float2bfloat16_rn(v.w);
            __nv_bfloat16 l0 = __float2bfloat16_rn(v.x - __bfloat162float(h0));
            __nv_bfloat16 l1 = __float2bfloat16_rn(v.y - __bfloat162float(h1));
            __nv_bfloat16 l2 = __float2bfloat16_rn(v.z - __bfloat162float(h2));
            __nv_bfloat16 l3 = __float2bfloat16_rn(v.w - __bfloat162float(h3));
            int o = row * LDS_K + kc;
            *(__nv_bfloat162*)&sBhi[o]     = __nv_bfloat162(h0, h1);
            *(__nv_bfloat162*)&sBhi[o + 2] = __nv_bfloat162(h2, h3);
            *(__nv_bfloat162*)&sBlo[o]     = __nv_bfloat162(l0, l1);
            *(__nv_bfloat162*)&sBlo[o + 2] = __nv_bfloat162(l2, l3);
        }
        __syncthreads();

        #pragma unroll
        for (int ks = 0; ks < 2; ks++) {
            const int k16 = ks * 16;
            wmma::fragment<wmma::matrix_a, 16, 16, 16, __nv_bfloat16, wmma::row_major> ahi[2], alo[2];
            #pragma unroll
            for (int mt = 0; mt < 2; mt++) {
                int r = wm * 32 + mt * 16;
                wmma::load_matrix_sync(ahi[mt], &sAhi[r * LDS_K + k16], LDS_K);
                wmma::load_matrix_sync(alo[mt], &sAlo[r * LDS_K + k16], LDS_K);
            }
            #pragma unroll
            for (int nt = 0; nt < 4; nt++) {
                int n = wn * 64 + nt * 16;
                wmma::fragment<wmma::matrix_b, 16, 16, 16, __nv_bfloat16, wmma::col_major> bhi, blo;
                wmma::load_matrix_sync(bhi, &sBhi[n * LDS_K + k16], LDS_K);
                wmma::load_matrix_sync(blo, &sBlo[n * LDS_K + k16], LDS_K);
                #pragma unroll
                for (int mt = 0; mt < 2; mt++) {
                    wmma::mma_sync(acc[mt][nt], ahi[mt], bhi, acc[mt][nt]);
                    wmma::mma_sync(acc[mt][nt], alo[mt], bhi, acc[mt][nt]);
                    wmma::mma_sync(acc[mt][nt], ahi[mt], blo, acc[mt][nt]);
                }
            }
        }
    }

    // epilogue
    __syncthreads();                     // bias tile no longer needed -> staging reuse
    #pragma unroll
    for (int mt = 0; mt < 2; mt++) {
        int r0 = row0 + wm * 32 + mt * 16;
        #pragma unroll
        for (int nt = 0; nt < 4; nt++) {
            int c0 = wn * 64 + nt * 16;
            if (TO_GH || r0 + 16 <= N_NODES) {
                wmma::store_matrix_sync(&dstp[r0 * OUTF + c0], acc[mt][nt], OUTF, wmma::mem_row_major);
            } else {
                float* st = sF + wid * 256;     // private 16x16 staging per warp
                wmma::store_matrix_sync(st, acc[mt][nt], 16, wmma::mem_row_major);
                __syncwarp();
                for (int i = lane; i < 256; i += 32) {
                    int rr = r0 + (i >> 4);
                    if (rr < N_NODES) dstp[rr * OUTF + c0 + (i & 15)] = st[i];
                }
                __syncwarp();
            }
        }
    }
}

// ---------------- launch: fork-join overlap of gemm1 with CSR build ----------------
extern "C" void kernel_launch(void* const* d_in, const int* in_sizes, int n_in,
                              void* d_out, int out_size) {
    const float* feat    = (const float*)d_in[0];
    const float* weight  = (const float*)d_in[1];
    const int*   src     = (const int*)d_in[2];
    const int*   dst     = (const int*)d_in[3];
    const float* W_pool  = (const float*)d_in[4];
    const float* b_pool  = (const float*)d_in[5];
    const float* W_neigh = (const float*)d_in[6];
    const float* b_neigh = (const float*)d_in[7];
    float*       out     = (float*)d_out;

    cudaFuncSetAttribute(gemm_wmma_kernel<D,  false, true>,
                         cudaFuncAttributeMaxDynamicSharedMemorySize, SMEM_SZ);
    cudaFuncSetAttribute(gemm_wmma_kernel<K2, true,  false>,
                         cudaFuncAttributeMaxDynamicSharedMemorySize, SMEM_SZ);

    const int GEMM_GRID = (N_NODES + TM - 1) / TM;   // 391

    // aux stream + fork/join events. kernel_launch runs only a handful of times
    // (correctness + capture); graph replays do not re-enter, so per-call
    // creation is bounded. Host objects only -- no device memory.
    cudaStream_t aux;
    cudaStreamCreate(&aux);
    cudaEvent_t evFork, evJoin;
    cudaEventCreateWithFlags(&evFork, cudaEventDisableTiming);
    cudaEventCreateWithFlags(&evJoin, cudaEventDisableTiming);

    cudaEventRecord(evFork, 0);
    cudaStreamWaitEvent(aux, evFork, 0);

    // main stream: CSR build chain
    zero_deg_kernel<<<(N_NODES + 255) / 256, 256>>>();
    hist_kernel<<<(N_EDGES + 255) / 256, 256>>>(dst);
    scan_kernel<<<1, 1024>>>();
    scatter_kernel<<<(N_EDGES + 255) / 256, 256>>>(src, dst, weight);

    // aux stream: gemm1 (independent of CSR build)
    gemm_wmma_kernel<D, false, true><<<GEMM_GRID, 256, SMEM_SZ, aux>>>(feat, W_pool, b_pool, nullptr);

    cudaEventRecord(evJoin, aux);
    cudaStreamWaitEvent(0, evJoin, 0);

    // main stream: reduce (needs scatter + gemm1), then gemm2
    reduce_kernel<<<(N_NODES + 7) / 8, 256>>>();
    gemm_wmma_kernel<K2, true, false><<<GEMM_GRID, 256, SMEM_SZ>>>(feat, W_neigh, b_neigh, out);
}

// round 12
// speedup vs baseline: 1.7818x; 1.4554x over previous
#include <cuda_runtime.h>
#include <cuda_bf16.h>
#include <mma.h>
#include <float.h>
#include <stdint.h>

using namespace nvcuda;

#define N_NODES 50000
#define N_PAD   50048
#define N_EDGES 640000
#define D       128
#define OUTF    128
#define TM      128
#define LDS_K   48
#define NBLK    49              // scan blocks of 1024 (49*1024 = 50176 >= N_NODES)

// ---------------- device scratch ----------------
__device__ __align__(16) float g_h[N_PAD * D];
__device__ __align__(16) float g_neigh[N_NODES * D];
__device__ int   g_deg[N_NODES];
__device__ int   g_start[N_NODES + 1];
__device__ int   g_cursor[N_NODES];
__device__ int   g_part[NBLK];
__device__ int   g_poff[64];
__device__ __align__(16) int   g_ssrc[N_EDGES];
__device__ __align__(16) float g_sw[N_EDGES];

__device__ __forceinline__ int clampN(int v) { return min(max(v, 0), N_NODES - 1); }

// ---------------- CSR build ----------------
__global__ void zero_deg_kernel() {
    int i = blockIdx.x * blockDim.x + threadIdx.x;
    if (i < N_NODES) g_deg[i] = 0;
}

__global__ void hist_kernel(const int* __restrict__ dst) {
    int e = blockIdx.x * blockDim.x + threadIdx.x;
    if (e < N_EDGES) atomicAdd(&g_deg[clampN(dst[e])], 1);
}

// scan p1: per-block (1024) partial sums
__global__ __launch_bounds__(1024) void scan_p1() {
    int t = threadIdx.x, idx = blockIdx.x * 1024 + t;
    int v = (idx < N_NODES) ? g_deg[idx] : 0;
    #pragma unroll
    for (int off = 16; off > 0; off >>= 1) v += __shfl_down_sync(0xFFFFFFFFu, v, off);
    __shared__ int sh[32];
    if ((t & 31) == 0) sh[t >> 5] = v;
    __syncthreads();
    if (t < 32) {
        int x = sh[t];
        #pragma unroll
        for (int off = 16; off > 0; off >>= 1) x += __shfl_down_sync(0xFFFFFFFFu, x, off);
        if (t == 0) g_part[blockIdx.x] = x;
    }
}

// scan p2: exclusive scan of NBLK partials (64-wide Hillis-Steele)
__global__ __launch_bounds__(64) void scan_p2() {
    __shared__ int sh[64];
    int t = threadIdx.x;
    int v = (t < NBLK) ? g_part[t] : 0;
    sh[t] = v;
    __syncthreads();
    #pragma unroll
    for (int off = 1; off < 64; off <<= 1) {
        int x = (t >= off) ? sh[t - off] : 0;
        __syncthreads();
        sh[t] += x;
        __syncthreads();
    }
    g_poff[t] = sh[t] - v;
}

// scan p3: block exclusive scan + block offset -> g_start / g_cursor
__global__ __launch_bounds__(1024) void scan_p3() {
    __shared__ int sh[1024];
    int b = blockIdx.x, t = threadIdx.x, idx = b * 1024 + t;
    int v = (idx < N_NODES) ? g_deg[idx] : 0;
    sh[t] = v;
    __syncthreads();
    #pragma unroll
    for (int off = 1; off < 1024; off <<= 1) {
        int x = (t >= off) ? sh[t - off] : 0;
        __syncthreads();
        sh[t] += x;
        __syncthreads();
    }
    int excl = sh[t] - v + g_poff[b];
    if (idx < N_NODES) { g_start[idx] = excl; g_cursor[idx] = excl; }
    if (idx == N_NODES - 1) g_start[N_NODES] = excl + v;
}

__global__ void scatter_kernel(const int* __restrict__ src, const int* __restrict__ dst,
                               const float* __restrict__ weight) {
    int e = blockIdx.x * blockDim.x + threadIdx.x;
    if (e >= N_EDGES) return;
    int d = clampN(dst[e]);
    int pos = atomicAdd(&g_cursor[d], 1);
    g_ssrc[pos] = clampN(src[e]);
    g_sw[pos]   = weight[e];
}

// ---------------- warp-per-node max reduce, float4 gather (R11-verbatim) ----------------
__global__ __launch_bounds__(256) void reduce_kernel() {
    const int node = (blockIdx.x << 3) + (threadIdx.x >> 5);
    const int lane = threadIdx.x & 31;
    if (node >= N_NODES) return;
    const int beg = g_start[node], end = g_start[node + 1];
    const int col = lane * 4;
    float4 acc = make_float4(-FLT_MAX, -FLT_MAX, -FLT_MAX, -FLT_MAX);
    int i = beg;
    for (; i + 4 <= end; i += 4) {
        int   s0 = g_ssrc[i],   s1 = g_ssrc[i+1], s2 = g_ssrc[i+2], s3 = g_ssrc[i+3];
        float w0 = g_sw[i],     w1 = g_sw[i+1],   w2 = g_sw[i+2],   w3 = g_sw[i+3];
        float4 v0 = *(const float4*)&g_h[s0*D + col];
        float4 v1 = *(const float4*)&g_h[s1*D + col];
        float4 v2 = *(const float4*)&g_h[s2*D + col];
        float4 v3 = *(const float4*)&g_h[s3*D + col];
        acc.x = fmaxf(acc.x, v0.x*w0); acc.y = fmaxf(acc.y, v0.y*w0);
        acc.z = fmaxf(acc.z, v0.z*w0); acc.w = fmaxf(acc.w, v0.w*w0);
        acc.x = fmaxf(acc.x, v1.x*w1); acc.y = fmaxf(acc.y, v1.y*w1);
        acc.z = fmaxf(acc.z, v1.z*w1); acc.w = fmaxf(acc.w, v1.w*w1);
        acc.x = fmaxf(acc.x, v2.x*w2); acc.y = fmaxf(acc.y, v2.y*w2);
        acc.z = fmaxf(acc.z, v2.z*w2); acc.w = fmaxf(acc.w, v2.w*w2);
        acc.x = fmaxf(acc.x, v3.x*w3); acc.y = fmaxf(acc.y, v3.y*w3);
        acc.z = fmaxf(acc.z, v3.z*w3); acc.w = fmaxf(acc.w, v3.w*w3);
    }
    for (; i < end; i++) {
        int s = g_ssrc[i];
        float w = g_sw[i];
        float4 v = *(const float4*)&g_h[s*D + col];
        acc.x = fmaxf(acc.x, v.x*w); acc.y = fmaxf(acc.y, v.y*w);
        acc.z = fmaxf(acc.z, v.z*w); acc.w = fmaxf(acc.w, v.w*w);
    }
    float4 outv = (beg == end) ? make_float4(0.f, 0.f, 0.f, 0.f) : acc;
    *(float4*)&g_neigh[node*D + col] = outv;
}

// ---------------- wmma bf16 3-pass GEMM, K=128 ----------------
// A_NEIGH: A matrix is device-global g_neigh (device symbol ref — shadow-ptr trap).
// TO_GH:   write to g_h. ACCUM: init acc from outp partial instead of bias.
static constexpr int SM_REG   = 128 * LDS_K;
static constexpr int SM_F_OFF = 4 * SM_REG * 2;
static constexpr int SMEM_SZ  = SM_F_OFF + 16 * 128 * 4;

template<bool A_NEIGH, int WSTR, bool TO_GH, bool ACCUM>
__global__ __launch_bounds__(256) void gemm_wmma_kernel(const float* __restrict__ A0,
                                                        const float* __restrict__ W,
                                                        const float* __restrict__ bias,
                                                        float* __restrict__ outp) {
    extern __shared__ char smem[];
    __nv_bfloat16* sAhi = (__nv_bfloat16*)smem;
    __nv_bfloat16* sAlo = sAhi + SM_REG;
    __nv_bfloat16* sBhi = sAlo + SM_REG;
    __nv_bfloat16* sBlo = sBhi + SM_REG;
    float*         sF   = (float*)(smem + SM_F_OFF);

    const int tid  = threadIdx.x;
    const int lane = tid & 31;
    const int wid  = tid >> 5;
    const int wm   = wid >> 1;
    const int wn   = wid & 1;
    const int row0 = blockIdx.x * TM;

    float* dstp = TO_GH ? g_h : outp;
    const float* Asrc = A_NEIGH ? (const float*)g_neigh : A0;

    wmma::fragment<wmma::accumulator, 16, 16, 16, float> acc[2][4];
    if (!ACCUM) {
        for (int i = tid; i < 16 * 128; i += 256) sF[i] = bias[i & 127];
        __syncthreads();
        #pragma unroll
        for (int mt = 0; mt < 2; mt++)
            #pragma unroll
            for (int nt = 0; nt < 4; nt++)
                wmma::load_matrix_sync(acc[mt][nt], sF + wn * 64 + nt * 16, 128, wmma::mem_row_major);
        __syncthreads();
    } else {
        // init from partial in outp
        #pragma unroll
        for (int mt = 0; mt < 2; mt++) {
            int r0 = row0 + wm * 32 + mt * 16;
            #pragma unroll
            for (int nt = 0; nt < 4; nt++) {
                int c0 = wn * 64 + nt * 16;
                if (r0 + 16 <= N_NODES) {
                    wmma::load_matrix_sync(acc[mt][nt], &outp[r0 * OUTF + c0], OUTF, wmma::mem_row_major);
                } else {
                    float* st = sF + wid * 256;
                    for (int i = lane; i < 256; i += 32) {
                        int rr = min(r0 + (i >> 4), N_NODES - 1);   // clamp; masked on store
                        st[i] = outp[rr * OUTF + c0 + (i & 15)];
                    }
                    __syncwarp();
                    wmma::load_matrix_sync(acc[mt][nt], st, 16, wmma::mem_row_major);
                    __syncwarp();
                }
            }
        }
        __syncthreads();
    }

    for (int c = 0; c < 4; c++) {           // K = 128, 4 chunks of 32
        const int k0 = c * 32;
        if (c > 0) __syncthreads();

        #pragma unroll
        for (int t = 0; t < 4; t++) {       // A chunk
            int g = tid + t * 256;
            int row = g >> 3, kc = (g & 7) * 4;
            int grow = row0 + row;
            float4 v = (grow < N_NODES) ? *(const float4*)&Asrc[grow * D + k0 + kc]
                                        : make_float4(0.f, 0.f, 0.f, 0.f);
            __nv_bfloat16 h0 = __float2bfloat16_rn(v.x), h1 = __float2bfloat16_rn(v.y);
            __nv_bfloat16 h2 = __float2bfloat16_rn(v.z), h3 = __float2bfloat16_rn(v.w);
            __nv_bfloat16 l0 = __float2bfloat16_rn(v.x - __bfloat162float(h0));
            __nv_bfloat16 l1 = __float2bfloat16_rn(v.y - __bfloat162float(h1));
            __nv_bfloat16 l2 = __float2bfloat16_rn(v.z - __bfloat162float(h2));
            __nv_bfloat16 l3 = __float2bfloat16_rn(v.w - __bfloat162float(h3));
            int o = row * LDS_K + kc;
            *(__nv_bfloat162*)&sAhi[o]     = __nv_bfloat162(h0, h1);
            *(__nv_bfloat162*)&sAhi[o + 2] = __nv_bfloat162(h2, h3);
            *(__nv_bfloat162*)&sAlo[o]     = __nv_bfloat162(l0, l1);
            *(__nv_bfloat162*)&sAlo[o + 2] = __nv_bfloat162(l2, l3);
        }
        #pragma unroll
        for (int t = 0; t < 4; t++) {       // B chunk: W[n][k], row stride WSTR
            int g = tid + t * 256;
            int row = g >> 3, kc = (g & 7) * 4;
            float4 v = *(const float4*)&W[row * WSTR + k0 + kc];
            __nv_bfloat16 h0 = __float2bfloat16_rn(v.x), h1 = __float2bfloat16_rn(v.y);
            __nv_bfloat16 h2 = __float2bfloat16_rn(v.z), h3 = __float2bfloat16_rn(v.w);
            __nv_bfloat16 l0 = __float2bfloat16_rn(v.x - __bfloat162float(h0));
            __nv_bfloat16 l1 = __float2bfloat16_rn(v.y - __bfloat162float(h1));
            __nv_bfloat16 l2 = __float2bfloat16_rn(v.z - __bfloat162float(h2));
            __nv_bfloat16 l3 = __float2bfloat16_rn(v.w - __bfloat162float(h3));
            int o = row * LDS_K + kc;
            *(__nv_bfloat162*)&sBhi[o]     = __nv_bfloat162(h0, h1);
            *(__nv_bfloat162*)&sBhi[o + 2] = __nv_bfloat162(h2, h3);
            *(__nv_bfloat162*)&sBlo[o]     = __nv_bfloat162(l0, l1);
            *(__nv_bfloat162*)&sBlo[o + 2] = __nv_bfloat162(l2, l3);
        }
        __syncthreads();

        #pragma unroll
        for (int ks = 0; ks < 2; ks++) {
            const int k16 = ks * 16;
            wmma::fragment<wmma::matrix_a, 16, 16, 16, __nv_bfloat16, wmma::row_major> ahi[2], alo[2];
            #pragma unroll
            for (int mt = 0; mt < 2; mt++) {
                int r = wm * 32 + mt * 16;
                wmma::load_matrix_sync(ahi[mt], &sAhi[r * LDS_K + k16], LDS_K);
                wmma::load_matrix_sync(alo[mt], &sAlo[r * LDS_K + k16], LDS_K);
            }
            #pragma unroll
            for (int nt = 0; nt < 4; nt++) {
                int n = wn * 64 + nt * 16;
                wmma::fragment<wmma::matrix_b, 16, 16, 16, __nv_bfloat16, wmma::col_major> bhi, blo;
                wmma::load_matrix_sync(bhi, &sBhi[n * LDS_K + k16], LDS_K);
                wmma::load_matrix_sync(blo, &sBlo[n * LDS_K + k16], LDS_K);
                #pragma unroll
                for (int mt = 0; mt < 2; mt++) {
                    wmma::mma_sync(acc[mt][nt], ahi[mt], bhi, acc[mt][nt]);
                    wmma::mma_sync(acc[mt][nt], alo[mt], bhi, acc[mt][nt]);
                    wmma::mma_sync(acc[mt][nt], ahi[mt], blo, acc[mt][nt]);
                }
            }
        }
    }

    // epilogue
    __syncthreads();
    #pragma unroll
    for (int mt = 0; mt < 2; mt++) {
        int r0 = row0 + wm * 32 + mt * 16;
        #pragma unroll
        for (int nt = 0; nt < 4; nt++) {
            int c0 = wn * 64 + nt * 16;
            if (TO_GH || r0 + 16 <= N_NODES) {
                wmma::store_matrix_sync(&dstp[r0 * OUTF + c0], acc[mt][nt], OUTF, wmma::mem_row_major);
            } else {
                float* st = sF + wid * 256;
                wmma::store_matrix_sync(st, acc[mt][nt], 16, wmma::mem_row_major);
                __syncwarp();
                for (int i = lane; i < 256; i += 32) {
                    int rr = r0 + (i >> 4);
                    if (rr < N_NODES) dstp[rr * OUTF + c0 + (i & 15)] = st[i];
                }
                __syncwarp();
            }
        }
    }
}

// ---------------- launch ----------------
extern "C" void kernel_launch(void* const* d_in, const int* in_sizes, int n_in,
                              void* d_out, int out_size) {
    const float* feat    = (const float*)d_in[0];
    const float* weight  = (const float*)d_in[1];
    const int*   src     = (const int*)d_in[2];
    const int*   dst     = (const int*)d_in[3];
    const float* W_pool  = (const float*)d_in[4];
    const float* b_pool  = (const float*)d_in[5];
    const float* W_neigh = (const float*)d_in[6];
    const float* b_neigh = (const float*)d_in[7];
    float*       out     = (float*)d_out;

    cudaFuncSetAttribute(gemm_wmma_kernel<false, 128, true,  false>,
                         cudaFuncAttributeMaxDynamicSharedMemorySize, SMEM_SZ);
    cudaFuncSetAttribute(gemm_wmma_kernel<false, 256, false, false>,
                         cudaFuncAttributeMaxDynamicSharedMemorySize, SMEM_SZ);
    cudaFuncSetAttribute(gemm_wmma_kernel<true,  256, false, true>,
                         cudaFuncAttributeMaxDynamicSharedMemorySize, SMEM_SZ);

    const int GEMM_GRID = (N_NODES + TM - 1) / TM;   // 391

    cudaStream_t aux;
    cudaStreamCreate(&aux);
    cudaEvent_t evFork, evJ1, evJ2;
    cudaEventCreateWithFlags(&evFork, cudaEventDisableTiming);
    cudaEventCreateWithFlags(&evJ1,   cudaEventDisableTiming);
    cudaEventCreateWithFlags(&evJ2,   cudaEventDisableTiming);

    cudaEventRecord(evFork, 0);
    cudaStreamWaitEvent(aux, evFork, 0);

    // main: CSR build chain
    zero_deg_kernel<<<(N_NODES + 255) / 256, 256>>>();
    hist_kernel<<<(N_EDGES + 255) / 256, 256>>>(dst);
    scan_p1<<<NBLK, 1024>>>();
    scan_p2<<<1, 64>>>();
    scan_p3<<<NBLK, 1024>>>();
    scatter_kernel<<<(N_EDGES + 255) / 256, 256>>>(src, dst, weight);

    // aux: gemm1 (-> g_h), then gemm2a (feat half of fc_neigh -> out partial)
    gemm_wmma_kernel<false, 128, true, false><<<GEMM_GRID, 256, SMEM_SZ, aux>>>(feat, W_pool, b_pool, nullptr);
    cudaEventRecord(evJ1, aux);
    gemm_wmma_kernel<false, 256, false, false><<<GEMM_GRID, 256, SMEM_SZ, aux>>>(feat, W_neigh, b_neigh, out);
    cudaEventRecord(evJ2, aux);

    // main: reduce needs scatter (main) + gemm1 (evJ1)
    cudaStreamWaitEvent(0, evJ1, 0);
    reduce_kernel<<<(N_NODES + 7) / 8, 256>>>();

    // main: gemm2b needs reduce (main) + gemm2a (evJ2); accumulates into out
    cudaStreamWaitEvent(0, evJ2, 0);
    gemm_wmma_kernel<true, 256, false, true><<<GEMM_GRID, 256, SMEM_SZ>>>(nullptr, W_neigh + D, b_neigh, out);
}